// round 10
// baseline (speedup 1.0000x reference)
#include <cuda_runtime.h>
#include <cuda_fp16.h>
#include <cstdint>

// ---------------------------------------------------------------------------
// LinearAttention on GB300 (sm_103a via compute_103 PTX)
// Round 9: fp16 mma GEMMs with 64x64 warp tiles (32 mma : 8 ldsm per k16 vs
// R8's 8:6) — tests whether the legacy HMMA pipe was issue-bound.
// Numerics identical to R8 (rel_err canary: 4.33e-4).
// B=4, S=4096, D=1024, H=16, hd=64
// ---------------------------------------------------------------------------

#define BATCH 4
#define SEQ   4096
#define EMB   1024
#define HEADS 16
#define HDIM  64
#define ROWS  (BATCH * SEQ)     // 16384
#define BH    (BATCH * HEADS)   // 64
#define SPLITS 16
#define SROWS (SEQ / SPLITS)    // 256

// GEMM tiling: CTA 128x128, 4 warps (2x2), warp tile 64x64
#define MT 128
#define NTT 128
#define KC 32
#define KCH (EMB / KC)          // 32
#define STAGES 3
#define G_THREADS 128
#define PITCH16B 80             // 32 halfs + 16B pad (ldmatrix conflict-free)
#define SZ_H16  (MT * PITCH16B)          // 10240
#define OFF_AH  0
#define OFF_BH  (SZ_H16)
#define STAGE_BYTES (2 * SZ_H16)         // 20480
#define SMEM_DYN (STAGES * STAGE_BYTES)  // 61440  -> 2 CTAs/SM

// ---------------------------------------------------------------------------
// Scratch (__device__ globals; allocation-free per harness rules)
// ---------------------------------------------------------------------------
__device__ __align__(256) float g_Q[(size_t)ROWS * EMB];
__device__ __align__(256) float g_K[(size_t)ROWS * EMB];
__device__ __align__(256) float g_V[(size_t)ROWS * EMB];
__device__ __align__(256) __half g_Xh[(size_t)ROWS * EMB];      // GEMM A operand
__device__ __align__(256) __half g_Wh[4][(size_t)EMB * EMB];    // weights [n][k]
__device__ float g_KVp[(size_t)SPLITS * BH * HDIM * HDIM];
__device__ float g_Ksump[(size_t)SPLITS * BH * HDIM];
__device__ float g_KV[(size_t)BH * HDIM * HDIM];
__device__ float g_Ksum[(size_t)BH * HDIM];

// ---------------------------------------------------------------------------
// helpers
// ---------------------------------------------------------------------------
__device__ __forceinline__ uint32_t smem_u32(const void* p) {
    uint32_t a;
    asm("{ .reg .u64 t; cvta.to.shared.u64 t, %1; cvt.u32.u64 %0, t; }" : "=r"(a) : "l"(p));
    return a;
}
__device__ __forceinline__ void cp16(uint32_t saddr, const void* gaddr) {
    asm volatile("cp.async.cg.shared.global [%0], [%1], 16;" :: "r"(saddr), "l"(gaddr) : "memory");
}
__device__ __forceinline__ void ldsm4(uint32_t& r0, uint32_t& r1, uint32_t& r2,
                                      uint32_t& r3, uint32_t addr) {
    asm volatile("ldmatrix.sync.aligned.m8n8.x4.shared.b16 {%0,%1,%2,%3}, [%4];"
                 : "=r"(r0), "=r"(r1), "=r"(r2), "=r"(r3) : "r"(addr));
}
__device__ __forceinline__ void mma_f16(float* c, const uint32_t* a, const uint32_t* b) {
    asm volatile(
        "mma.sync.aligned.m16n8k16.row.col.f32.f16.f16.f32 "
        "{%0,%1,%2,%3}, {%4,%5,%6,%7}, {%8,%9}, {%0,%1,%2,%3};"
        : "+f"(c[0]), "+f"(c[1]), "+f"(c[2]), "+f"(c[3])
        : "r"(a[0]), "r"(a[1]), "r"(a[2]), "r"(a[3]), "r"(b[0]), "r"(b[1]));
}

// ---------------------------------------------------------------------------
// GEMM: C[M,N] = A @ Bt^T + bias (+elu+1); A,Bt fp16; C fp32.
// Grid (8, 128), 128 threads, 4 warps of 64x64, 3-stage cp.async, 2 CTAs/SM.
// ---------------------------------------------------------------------------
__global__ __launch_bounds__(G_THREADS, 2) void gemm_f16(
    const __half* __restrict__ A, const __half* __restrict__ B,
    const float* __restrict__ bias, float* __restrict__ C, int elu_mode)
{
    extern __shared__ char dsm[];
    const uint32_t dyn = smem_u32(dsm);

    const int tid  = threadIdx.x;
    const int wid  = tid >> 5;
    const int lane = tid & 31;
    const int m0 = blockIdx.y * MT;
    const int n0 = blockIdx.x * NTT;
    const int wm = (wid >> 1) * 64;     // warp row offset (0 / 64)
    const int wn = (wid & 1) * 64;      // warp col offset (0 / 64)

    // stage loader: A 128x4 + B 128x4 granules (16B) = 1024, 8 per thread
    auto load_stage = [&](int ch) {
        const int st = ch % STAGES;
        const uint32_t sb = dyn + (uint32_t)st * STAGE_BYTES;
        const int k0 = ch * KC;
        #pragma unroll
        for (int i = tid; i < 1024; i += G_THREADS) {
            const int half = i >> 9;         // 0=A 1=B
            const int rem  = i & 511;
            const int rr   = rem >> 2;
            const int g    = rem & 3;
            const __half* gp = half ? B : A;
            const int row = (half ? n0 : m0) + rr;
            cp16(sb + (uint32_t)half * SZ_H16 + (uint32_t)rr * PITCH16B + g * 16u,
                 gp + (size_t)row * EMB + k0 + g * 8);
        }
        asm volatile("cp.async.commit_group;" ::: "memory");
    };

    float acc[4][8][4];
    #pragma unroll
    for (int i = 0; i < 4; i++)
        #pragma unroll
        for (int j = 0; j < 8; j++)
            #pragma unroll
            for (int q = 0; q < 4; q++) acc[i][j][q] = 0.f;

    #pragma unroll
    for (int s = 0; s < STAGES - 1; s++) load_stage(s);

    for (int ch = 0; ch < KCH; ch++) {
        if (ch + STAGES - 1 < KCH) load_stage(ch + STAGES - 1);
        else asm volatile("cp.async.commit_group;" ::: "memory");
        asm volatile("cp.async.wait_group %0;" :: "n"(STAGES - 1) : "memory");
        __syncthreads();

        const uint32_t sb = dyn + (uint32_t)(ch % STAGES) * STAGE_BYTES;

        #pragma unroll
        for (int ks = 0; ks < 2; ks++) {
            const int kl = ks * 16;
            const int a_row = wm + (lane & 15);
            const int a_col = kl + (lane >> 4) * 8;
            const int b_row = wn + (lane & 7) + ((lane >> 4) & 1) * 8;
            const int b_col = kl + ((lane >> 3) & 1) * 8;

            uint32_t af[4][4];
            #pragma unroll
            for (int fm = 0; fm < 4; fm++) {
                uint32_t off = (uint32_t)(a_row + fm * 16) * PITCH16B + (uint32_t)a_col * 2u;
                ldsm4(af[fm][0], af[fm][1], af[fm][2], af[fm][3], sb + OFF_AH + off);
            }
            uint32_t bf[4][4];
            #pragma unroll
            for (int fp = 0; fp < 4; fp++) {
                uint32_t off = (uint32_t)(b_row + fp * 16) * PITCH16B + (uint32_t)b_col * 2u;
                ldsm4(bf[fp][0], bf[fp][1], bf[fp][2], bf[fp][3], sb + OFF_BH + off);
            }
            #pragma unroll
            for (int fm = 0; fm < 4; fm++)
                #pragma unroll
                for (int fn = 0; fn < 8; fn++)
                    mma_f16(acc[fm][fn], af[fm], &bf[fn >> 1][(fn & 1) * 2]);
        }
        __syncthreads();
    }

    // ---- epilogue: bias (+elu+1), fp32 stores ----
    const int er = lane >> 2;           // 0..7
    const int ec = (lane & 3) * 2;      // 0,2,4,6
    #pragma unroll
    for (int fn = 0; fn < 8; fn++) {
        const int col = n0 + wn + fn * 8 + ec;
        const float b0 = bias[col], b1 = bias[col + 1];
        #pragma unroll
        for (int fm = 0; fm < 4; fm++) {
            const int row = m0 + wm + fm * 16 + er;
            #pragma unroll
            for (int h = 0; h < 2; h++) {
                float v0 = acc[fm][fn][2 * h + 0] + b0;
                float v1 = acc[fm][fn][2 * h + 1] + b1;
                if (elu_mode) {
                    v0 = (v0 > 0.f) ? (v0 + 1.f) : __expf(v0);
                    v1 = (v1 > 0.f) ? (v1 + 1.f) : __expf(v1);
                }
                *(float2*)(C + (size_t)(row + 8 * h) * EMB + col) = make_float2(v0, v1);
            }
        }
    }
}

// ---------------------------------------------------------------------------
// fp32 -> fp16 (elementwise, float4-vectorized)
// ---------------------------------------------------------------------------
__global__ __launch_bounds__(256) void conv_f16(
    const float* __restrict__ X, __half* __restrict__ H)
{
    size_t i = ((size_t)blockIdx.x * 256 + threadIdx.x) * 4;
    float4 v = *(const float4*)(X + i);
    ushort4 hv;
    hv.x = __half_as_ushort(__float2half_rn(v.x));
    hv.y = __half_as_ushort(__float2half_rn(v.y));
    hv.z = __half_as_ushort(__float2half_rn(v.z));
    hv.w = __half_as_ushort(__float2half_rn(v.w));
    *(ushort4*)(H + i) = hv;
}

// ---------------------------------------------------------------------------
// Weight transpose + fp16: Wt[n][k] = W[k][n]
// ---------------------------------------------------------------------------
__global__ __launch_bounds__(256) void conv_w_t(
    const float* __restrict__ W, __half* __restrict__ H)
{
    __shared__ float tile[32][33];
    const int n0 = blockIdx.x * 32, k0 = blockIdx.y * 32;
    const int tx = threadIdx.x & 31, ty = threadIdx.x >> 5;  // 32x8
    #pragma unroll
    for (int j = 0; j < 32; j += 8)
        tile[ty + j][tx] = W[(size_t)(k0 + ty + j) * EMB + n0 + tx];
    __syncthreads();
    #pragma unroll
    for (int j = 0; j < 32; j += 8)
        H[(size_t)(n0 + ty + j) * EMB + k0 + tx] = __float2half_rn(tile[tx][ty + j]);
}

// ---------------------------------------------------------------------------
// KV summarization: KV[b,h,d,e] = sum_s K[:,d]*V[:,e]; Ksum[b,h,d]
// Register-tiled 4x4 per thread, float4 LDS.
// ---------------------------------------------------------------------------
#define KVCH 16

__global__ __launch_bounds__(256) void kv_partial()
{
    const int bh = blockIdx.x, sp = blockIdx.y;
    const int b = bh / HEADS, h = bh % HEADS;
    const int t = threadIdx.x;
    const int d0 = (t & 15) * 4;
    const int e0 = (t >> 4) * 4;

    __shared__ float Ks[KVCH][HDIM];
    __shared__ float Vs[KVCH][HDIM];

    float acc[4][4];
    #pragma unroll
    for (int i = 0; i < 4; i++)
        #pragma unroll
        for (int j = 0; j < 4; j++) acc[i][j] = 0.f;
    float ksum[4] = {0.f, 0.f, 0.f, 0.f};

    const float* Kbase = g_K + (size_t)b * SEQ * EMB + h * HDIM;
    const float* Vbase = g_V + (size_t)b * SEQ * EMB + h * HDIM;

    const int lr = t >> 4, lc = (t & 15) * 4;   // 16 rows x 16 float4
    const int s_begin = sp * SROWS;
    for (int s0 = s_begin; s0 < s_begin + SROWS; s0 += KVCH) {
        *(float4*)&Ks[lr][lc] = *(const float4*)(Kbase + (size_t)(s0 + lr) * EMB + lc);
        *(float4*)&Vs[lr][lc] = *(const float4*)(Vbase + (size_t)(s0 + lr) * EMB + lc);
        __syncthreads();
        #pragma unroll
        for (int ss = 0; ss < KVCH; ss++) {
            float4 kk = *(const float4*)&Ks[ss][d0];
            float4 vv = *(const float4*)&Vs[ss][e0];
            const float* kp = (const float*)&kk;
            const float* vp = (const float*)&vv;
            #pragma unroll
            for (int i = 0; i < 4; i++) {
                ksum[i] += kp[i];
                #pragma unroll
                for (int j = 0; j < 4; j++)
                    acc[i][j] += kp[i] * vp[j];
            }
        }
        __syncthreads();
    }

    float* KVp = g_KVp + ((size_t)sp * BH + bh) * HDIM * HDIM;
    #pragma unroll
    for (int i = 0; i < 4; i++)
        *(float4*)(KVp + (size_t)(d0 + i) * HDIM + e0) = *(float4*)acc[i];
    if (t < 16) {
        #pragma unroll
        for (int i = 0; i < 4; i++)
            g_Ksump[((size_t)sp * BH + bh) * HDIM + d0 + i] = ksum[i];
    }
}

__global__ __launch_bounds__(256) void kv_reduce()
{
    const int bh = blockIdx.x;
    const int t = threadIdx.x;
    for (int i = t; i < HDIM * HDIM; i += 256) {
        float s = 0.f;
        #pragma unroll
        for (int sp = 0; sp < SPLITS; sp++)
            s += g_KVp[((size_t)sp * BH + bh) * HDIM * HDIM + i];
        g_KV[(size_t)bh * HDIM * HDIM + i] = s;
    }
    if (t < HDIM) {
        float s = 0.f;
        #pragma unroll
        for (int sp = 0; sp < SPLITS; sp++)
            s += g_Ksump[((size_t)sp * BH + bh) * HDIM + t];
        g_Ksum[(size_t)bh * HDIM + t] = s;
    }
}

// ---------------------------------------------------------------------------
// Apply: attn = (Q·KV)/(Q·Ksum+1e-6); writes fp16 operand directly.
// ---------------------------------------------------------------------------
__global__ __launch_bounds__(256) void apply_attn()
{
    const int stile = blockIdx.x;
    const int bh = blockIdx.y;
    const int b = bh / HEADS, h = bh % HEADS;
    const int t = threadIdx.x;

    __shared__ float Qt[HDIM][64];      // Qt[d][row]
    __shared__ float KVs[HDIM][HDIM];
    __shared__ float Ksums[HDIM];

    const int s0 = stile * 64;
    const float* Qbase = g_Q + (size_t)(b * SEQ + s0) * EMB + h * HDIM;

    #pragma unroll
    for (int k = 0; k < 16; k++) {
        int idx = t + 256 * k;
        int rr = idx >> 6, cc = idx & 63;
        Qt[cc][rr] = Qbase[(size_t)rr * EMB + cc];
        KVs[rr][cc] = g_KV[(size_t)bh * HDIM * HDIM + idx];
    }
    if (t < HDIM) Ksums[t] = g_Ksum[(size_t)bh * HDIM + t];
    __syncthreads();

    const int r0 = (t & 15) * 4;
    const int e0 = (t >> 4) * 4;

    float acc[4][4];
    #pragma unroll
    for (int i = 0; i < 4; i++)
        #pragma unroll
        for (int j = 0; j < 4; j++) acc[i][j] = 0.f;
    float nrm[4] = {0.f, 0.f, 0.f, 0.f};

    #pragma unroll
    for (int dd = 0; dd < HDIM; dd++) {
        float4 qq = *(const float4*)&Qt[dd][r0];
        float4 vv = *(const float4*)&KVs[dd][e0];
        const float* qp = (const float*)&qq;
        const float* vp = (const float*)&vv;
        float ks = Ksums[dd];
        #pragma unroll
        for (int i = 0; i < 4; i++) {
            nrm[i] += qp[i] * ks;
            #pragma unroll
            for (int j = 0; j < 4; j++)
                acc[i][j] += qp[i] * vp[j];
        }
    }

    #pragma unroll
    for (int i = 0; i < 4; i++) {
        float inv = 1.f / (nrm[i] + 1e-6f);
        size_t obase = (size_t)(b * SEQ + s0 + r0 + i) * EMB + h * HDIM + e0;
        ushort4 hv;
        hv.x = __half_as_ushort(__float2half_rn(acc[i][0] * inv));
        hv.y = __half_as_ushort(__float2half_rn(acc[i][1] * inv));
        hv.z = __half_as_ushort(__float2half_rn(acc[i][2] * inv));
        hv.w = __half_as_ushort(__float2half_rn(acc[i][3] * inv));
        *(ushort4*)(g_Xh + obase) = hv;
    }
}

// ---------------------------------------------------------------------------
// Launch
// ---------------------------------------------------------------------------
extern "C" void kernel_launch(void* const* d_in, const int* in_sizes, int n_in,
                              void* d_out, int out_size)
{
    const float* query = (const float*)d_in[0];
    const float* keyv  = (const float*)d_in[1];
    const float* W[4] = { (const float*)d_in[2], (const float*)d_in[4],
                          (const float*)d_in[6], (const float*)d_in[8] };
    const float* bq = (const float*)d_in[3];
    const float* bk = (const float*)d_in[5];
    const float* bv = (const float*)d_in[7];
    const float* bo = (const float*)d_in[9];
    float* out = (float*)d_out;

    float *pQ, *pK, *pV;
    __half *pXh;
    __half (*pWh)[(size_t)EMB * EMB];
    cudaGetSymbolAddress((void**)&pQ, g_Q);
    cudaGetSymbolAddress((void**)&pK, g_K);
    cudaGetSymbolAddress((void**)&pV, g_V);
    cudaGetSymbolAddress((void**)&pXh, g_Xh);
    cudaGetSymbolAddress((void**)&pWh, g_Wh);

    static bool attr_set = false;
    if (!attr_set) {
        cudaFuncSetAttribute(gemm_f16, cudaFuncAttributeMaxDynamicSharedMemorySize, SMEM_DYN);
        attr_set = true;
    }

    const dim3 wgrid(EMB / 32, EMB / 32);              // (32, 32)
    const dim3 ggrid(EMB / NTT, ROWS / MT);            // (8, 128)
    const int conv_blocks = (int)(((size_t)ROWS * EMB / 4) / 256);  // 16384

    // Weight transpose + convert
    for (int w = 0; w < 4; w++)
        conv_w_t<<<wgrid, 256>>>(W[w], pWh[w]);

    // Q projection (elu+1 fused)
    conv_f16<<<conv_blocks, 256>>>(query, pXh);
    gemm_f16<<<ggrid, G_THREADS, SMEM_DYN>>>(pXh, pWh[0], bq, pQ, 1);

    // K/V projections (share key_value conversion)
    conv_f16<<<conv_blocks, 256>>>(keyv, pXh);
    gemm_f16<<<ggrid, G_THREADS, SMEM_DYN>>>(pXh, pWh[1], bk, pK, 1);
    gemm_f16<<<ggrid, G_THREADS, SMEM_DYN>>>(pXh, pWh[2], bv, pV, 0);

    // Linear-attention core (fp32)
    kv_partial<<<dim3(BH, SPLITS), 256>>>();
    kv_reduce<<<BH, 256>>>();
    apply_attn<<<dim3(SEQ / 64, BH), 256>>>();   // emits fp16 operand into g_Xh

    // Output projection
    gemm_f16<<<ggrid, G_THREADS, SMEM_DYN>>>(pXh, pWh[3], bo, out, 0);
}